// round 4
// baseline (speedup 1.0000x reference)
#include <cuda_runtime.h>
#include <stdint.h>

// Problem constants
#define BATCH 32
#define NSEQ  512
#define CDIM  1024
#define NHEAD 16
#define HDIM  64
#define QKSCALE 0.125f

// Scratch (device globals — no allocations allowed in kernel_launch)
__device__ float g_qkv[(size_t)BATCH * NSEQ * 3 * CDIM];   // [B, N, 3C]  (q | k | v)
__device__ float g_ao [(size_t)BATCH * NSEQ * CDIM];       // [B, N, C]   attention output

// ---------------------------------------------------------------------------
// helpers
// ---------------------------------------------------------------------------
__device__ __forceinline__ uint32_t f2tf(float x) {
    uint32_t r;
    asm("cvt.rna.tf32.f32 %0, %1;" : "=r"(r) : "f"(x));
    return r;
}

__device__ __forceinline__ void mma8(float c[4], const uint32_t a[4], const uint32_t b[2]) {
    asm volatile(
        "mma.sync.aligned.m16n8k8.row.col.f32.tf32.tf32.f32 "
        "{%0,%1,%2,%3}, {%4,%5,%6,%7}, {%8,%9}, {%0,%1,%2,%3};\n"
        : "+f"(c[0]), "+f"(c[1]), "+f"(c[2]), "+f"(c[3])
        : "r"(a[0]), "r"(a[1]), "r"(a[2]), "r"(a[3]), "r"(b[0]), "r"(b[1]));
}

__device__ __forceinline__ void cpa16(uint32_t s, const void* g) {
    asm volatile("cp.async.cg.shared.global [%0], [%1], 16;\n" :: "r"(s), "l"(g));
}
__device__ __forceinline__ void cpcommit() { asm volatile("cp.async.commit_group;\n"); }
template <int N> __device__ __forceinline__ void cpwait() {
    asm volatile("cp.async.wait_group %0;\n" :: "n"(N));
}

// ---------------------------------------------------------------------------
// Generic GEMM:  C[M,N] = A[M,K] * W[N,K]^T (+ bias)
// A row-major (lda=K), W row-major (ldb=K), C row-major (ldc=N).
// Tile 128x128, BK=16, 256 threads, 8 warps (4m x 2n), cp.async double buffer.
// ---------------------------------------------------------------------------
#define GBM 128
#define GBN 128
#define GBK 16
#define GST 20   // smem k-stride (pad: 20 mod 32 = 4*odd -> conflict-free frag LDS)

__global__ void __launch_bounds__(256, 2)
gemm_tf32_kernel(const float* __restrict__ A, const float* __restrict__ W,
                 float* __restrict__ C, const float* __restrict__ bias,
                 int K, int N)
{
    __shared__ float As[2][GBM * GST];
    __shared__ float Bs[2][GBN * GST];

    const int tid  = threadIdx.x;
    const int lane = tid & 31;
    const int warp = tid >> 5;
    const int wm   = warp >> 1;   // 0..3
    const int wn   = warp & 1;    // 0..1

    const int m0 = blockIdx.y * GBM;
    const int n0 = blockIdx.x * GBN;

    float acc[2][8][4];
#pragma unroll
    for (int i = 0; i < 2; i++)
#pragma unroll
        for (int j = 0; j < 8; j++)
#pragma unroll
            for (int k = 0; k < 4; k++) acc[i][j][k] = 0.f;

    const int lrow = tid >> 2;        // 0..63
    const int lq   = (tid & 3) * 4;   // 0,4,8,12

    const float* Ag = A + (size_t)m0 * K;
    const float* Wg = W + (size_t)n0 * K;

    const int nk = K / GBK;

    // prologue: stage 0
    {
        uint32_t sA = (uint32_t)__cvta_generic_to_shared(&As[0][0]);
        uint32_t sB = (uint32_t)__cvta_generic_to_shared(&Bs[0][0]);
#pragma unroll
        for (int t = 0; t < 2; t++) {
            int row = lrow + t * 64;
            cpa16(sA + (uint32_t)(row * GST + lq) * 4, Ag + (size_t)row * K + lq);
            cpa16(sB + (uint32_t)(row * GST + lq) * 4, Wg + (size_t)row * K + lq);
        }
        cpcommit();
    }

    for (int kc = 0; kc < nk; kc++) {
        if (kc + 1 < nk) {
            int buf = (kc + 1) & 1;
            int k0  = (kc + 1) * GBK;
            uint32_t sA = (uint32_t)__cvta_generic_to_shared(&As[buf][0]);
            uint32_t sB = (uint32_t)__cvta_generic_to_shared(&Bs[buf][0]);
#pragma unroll
            for (int t = 0; t < 2; t++) {
                int row = lrow + t * 64;
                cpa16(sA + (uint32_t)(row * GST + lq) * 4, Ag + (size_t)row * K + k0 + lq);
                cpa16(sB + (uint32_t)(row * GST + lq) * 4, Wg + (size_t)row * K + k0 + lq);
            }
            cpcommit();
            cpwait<1>();
        } else {
            cpwait<0>();
        }
        __syncthreads();

        const float* As_ = &As[kc & 1][0];
        const float* Bs_ = &Bs[kc & 1][0];

#pragma unroll
        for (int ks = 0; ks < 2; ks++) {
            const int kk = ks * 8;
            uint32_t af[2][4];
#pragma unroll
            for (int mi = 0; mi < 2; mi++) {
                const int r = wm * 32 + mi * 16 + (lane >> 2);
                const float* p = As_ + r * GST + kk + (lane & 3);
                af[mi][0] = f2tf(p[0]);
                af[mi][1] = f2tf(p[8 * GST]);
                af[mi][2] = f2tf(p[4]);
                af[mi][3] = f2tf(p[8 * GST + 4]);
            }
#pragma unroll
            for (int ni = 0; ni < 8; ni++) {
                const int c = wn * 64 + ni * 8 + (lane >> 2);
                const float* p = Bs_ + c * GST + kk + (lane & 3);
                uint32_t bf[2] = { f2tf(p[0]), f2tf(p[4]) };
                mma8(acc[0][ni], af[0], bf);
                mma8(acc[1][ni], af[1], bf);
            }
        }
        __syncthreads();
    }

    // epilogue
#pragma unroll
    for (int mi = 0; mi < 2; mi++) {
#pragma unroll
        for (int ni = 0; ni < 8; ni++) {
            const int r = m0 + wm * 32 + mi * 16 + (lane >> 2);
            const int c = n0 + wn * 64 + ni * 8 + 2 * (lane & 3);
            float b0 = bias ? bias[c]     : 0.f;
            float b1 = bias ? bias[c + 1] : 0.f;
            float2 v0 = make_float2(acc[mi][ni][0] + b0, acc[mi][ni][1] + b1);
            float2 v1 = make_float2(acc[mi][ni][2] + b0, acc[mi][ni][3] + b1);
            *reinterpret_cast<float2*>(C + (size_t)r * N + c)       = v0;
            *reinterpret_cast<float2*>(C + (size_t)(r + 8) * N + c) = v1;
        }
    }
}

// ---------------------------------------------------------------------------
// Attention: one CTA per (b, h, 64-row q block). 256 threads, 8 warps.
// Full 64x512 scores in smem; K/V streamed in 64-key chunks.
// QK^T uses hi/lo tf32 split (3 mmas) for accuracy; PV plain tf32.
// ---------------------------------------------------------------------------
#define SST 516   // scores stride (516 mod 32 = 4 -> conflict-free A frags)
#define QST 68    // Q tile stride
#define KCH 68    // K chunk stride
#define VST 68    // V chunk stride (transposed [hd][key])

#define OFF_SS 0
#define OFF_QS (64 * SST)                       // 33024
#define OFF_KV (OFF_QS + 64 * QST)              // 37376
#define OFF_MS (OFF_KV + 2 * 64 * KCH)          // 46080
#define OFF_RS (OFF_MS + NSEQ)                  // 46592
#define SMEM_FLOATS (OFF_RS + 64)               // 46656
#define SMEM_BYTES (SMEM_FLOATS * 4)            // 186624

__global__ void __launch_bounds__(256, 1)
attn_kernel(const float* __restrict__ mask)
{
    extern __shared__ float sm[];
    float* Ss  = sm + OFF_SS;
    float* Qs  = sm + OFF_QS;
    float* KV0 = sm + OFF_KV;
    float* Ms  = sm + OFF_MS;
    float* Rs  = sm + OFF_RS;

    const int tid  = threadIdx.x;
    const int lane = tid & 31;
    const int warp = tid >> 5;
    const int wm   = warp >> 1;   // 0..3 : 16-row group
    const int wn   = warp & 1;    // 0..1 : column half

    const int qb = blockIdx.x;    // 0..7
    const int bh = blockIdx.y;    // 0..511
    const int b  = bh >> 4;
    const int h  = bh & 15;

    const float* qbase = g_qkv + ((size_t)(b * NSEQ + qb * 64) * (3 * CDIM)) + h * HDIM;
    const float* kbase = g_qkv + ((size_t)(b * NSEQ) * (3 * CDIM)) + CDIM + h * HDIM;
    const float* vbase = g_qkv + ((size_t)(b * NSEQ) * (3 * CDIM)) + 2 * CDIM + h * HDIM;

    // ---- load Q tile (64x64) + mask row ----
#pragma unroll
    for (int t = 0; t < 4; t++) {
        int idx = tid + t * 256;          // 0..1023
        int row = idx >> 4;               // 0..63
        int q4  = (idx & 15) * 4;
        float4 v = *reinterpret_cast<const float4*>(qbase + (size_t)row * (3 * CDIM) + q4);
        *reinterpret_cast<float4*>(Qs + row * QST + q4) = v;
    }
    Ms[tid]       = mask[b * NSEQ + tid];
    Ms[tid + 256] = mask[b * NSEQ + tid + 256];

    // ---- S phase: stream K chunks (cp.async double buffer) ----
    {
        uint32_t s = (uint32_t)__cvta_generic_to_shared(KV0);
#pragma unroll
        for (int t = 0; t < 4; t++) {
            int idx = tid + t * 256;
            int row = idx >> 4;
            int q4  = (idx & 15) * 4;
            cpa16(s + (uint32_t)(row * KCH + q4) * 4,
                  kbase + (size_t)row * (3 * CDIM) + q4);
        }
        cpcommit();
    }

    for (int kc = 0; kc < 8; kc++) {
        if (kc + 1 < 8) {
            uint32_t s = (uint32_t)__cvta_generic_to_shared(KV0 + ((kc + 1) & 1) * (64 * KCH));
#pragma unroll
            for (int t = 0; t < 4; t++) {
                int idx = tid + t * 256;
                int row = idx >> 4;
                int q4  = (idx & 15) * 4;
                cpa16(s + (uint32_t)(row * KCH + q4) * 4,
                      kbase + (size_t)((kc + 1) * 64 + row) * (3 * CDIM) + q4);
            }
            cpcommit();
            cpwait<1>();
        } else {
            cpwait<0>();
        }
        __syncthreads();

        const float* Ks = KV0 + (kc & 1) * (64 * KCH);
        float sacc[4][4];
#pragma unroll
        for (int i = 0; i < 4; i++)
#pragma unroll
            for (int j = 0; j < 4; j++) sacc[i][j] = 0.f;

#pragma unroll
        for (int ks = 0; ks < 8; ks++) {
            const int kk = ks * 8;
            uint32_t ah[4], al[4];
            {
                const int r = wm * 16 + (lane >> 2);
                const float* p = Qs + r * QST + kk + (lane & 3);
                float f0 = p[0], f1 = p[8 * QST], f2 = p[4], f3 = p[8 * QST + 4];
                ah[0] = f2tf(f0); ah[1] = f2tf(f1); ah[2] = f2tf(f2); ah[3] = f2tf(f3);
                al[0] = f2tf(f0 - __uint_as_float(ah[0]));
                al[1] = f2tf(f1 - __uint_as_float(ah[1]));
                al[2] = f2tf(f2 - __uint_as_float(ah[2]));
                al[3] = f2tf(f3 - __uint_as_float(ah[3]));
            }
#pragma unroll
            for (int ni = 0; ni < 4; ni++) {
                const int c = wn * 32 + ni * 8 + (lane >> 2);
                const float* p = Ks + c * KCH + kk + (lane & 3);
                float g0 = p[0], g1 = p[4];
                uint32_t bh2[2] = { f2tf(g0), f2tf(g1) };
                uint32_t bl2[2] = { f2tf(g0 - __uint_as_float(bh2[0])),
                                    f2tf(g1 - __uint_as_float(bh2[1])) };
                mma8(sacc[ni], ah, bh2);   // hi*hi
                mma8(sacc[ni], al, bh2);   // lo*hi
                mma8(sacc[ni], ah, bl2);   // hi*lo
            }
        }

        // write scores (scale + key-mask bias; query-mask term is softmax-invariant)
#pragma unroll
        for (int ni = 0; ni < 4; ni++) {
            const int r  = wm * 16 + (lane >> 2);
            const int cc = kc * 64 + wn * 32 + ni * 8 + 2 * (lane & 3);
            Ss[r * SST + cc]           = sacc[ni][0] * QKSCALE + Ms[cc];
            Ss[r * SST + cc + 1]       = sacc[ni][1] * QKSCALE + Ms[cc + 1];
            Ss[(r + 8) * SST + cc]     = sacc[ni][2] * QKSCALE + Ms[cc];
            Ss[(r + 8) * SST + cc + 1] = sacc[ni][3] * QKSCALE + Ms[cc + 1];
        }
        __syncthreads();
    }

    // ---- softmax (each warp owns 8 rows) ----
#pragma unroll 1
    for (int rr = 0; rr < 8; rr++) {
        const int r = warp * 8 + rr;
        float* srow = Ss + r * SST;
        float mx = -1e30f;
#pragma unroll
        for (int j = 0; j < 16; j++) mx = fmaxf(mx, srow[lane + j * 32]);
#pragma unroll
        for (int o = 16; o > 0; o >>= 1) mx = fmaxf(mx, __shfl_xor_sync(0xffffffffu, mx, o));
        float sum = 0.f;
#pragma unroll
        for (int j = 0; j < 16; j++) {
            float e = __expf(srow[lane + j * 32] - mx);
            srow[lane + j * 32] = e;
            sum += e;
        }
#pragma unroll
        for (int o = 16; o > 0; o >>= 1) sum += __shfl_xor_sync(0xffffffffu, sum, o);
        if (lane == 0) Rs[r] = 1.f / sum;
    }
    __syncthreads();

    // ---- PV phase: O[64,64] += P[64,512] @ V[512,64], V chunks of 64 keys ----
    float oacc[4][4];
#pragma unroll
    for (int i = 0; i < 4; i++)
#pragma unroll
        for (int j = 0; j < 4; j++) oacc[i][j] = 0.f;

    float* Vs = KV0;  // reuse, [64 hd][VST] transposed
    for (int vc = 0; vc < 8; vc++) {
#pragma unroll
        for (int t = 0; t < 4; t++) {
            int idx = tid + t * 256;
            int key = idx & 63;
            int qq  = (idx >> 6) * 4;    // hd base: 0..60
            float4 v = *reinterpret_cast<const float4*>(
                vbase + (size_t)(vc * 64 + key) * (3 * CDIM) + qq);
            Vs[(qq + 0) * VST + key] = v.x;
            Vs[(qq + 1) * VST + key] = v.y;
            Vs[(qq + 2) * VST + key] = v.z;
            Vs[(qq + 3) * VST + key] = v.w;
        }
        __syncthreads();

#pragma unroll
        for (int ks = 0; ks < 8; ks++) {
            uint32_t af[4];
            {
                const int r = wm * 16 + (lane >> 2);
                const float* p = Ss + r * SST + vc * 64 + ks * 8 + (lane & 3);
                af[0] = f2tf(p[0]);
                af[1] = f2tf(p[8 * SST]);
                af[2] = f2tf(p[4]);
                af[3] = f2tf(p[8 * SST + 4]);
            }
#pragma unroll
            for (int ni = 0; ni < 4; ni++) {
                const int n = wn * 32 + ni * 8 + (lane >> 2);
                const float* p = Vs + n * VST + ks * 8 + (lane & 3);
                uint32_t bf[2] = { f2tf(p[0]), f2tf(p[4]) };
                mma8(oacc[ni], af, bf);
            }
        }
        __syncthreads();
    }

    // ---- epilogue: normalize rows, write to g_ao[b, n, h*64 + hd] ----
    float* aob = g_ao + ((size_t)(b * NSEQ + qb * 64) * CDIM) + h * HDIM;
    const int r = wm * 16 + (lane >> 2);
    const float inv0 = Rs[r];
    const float inv1 = Rs[r + 8];
#pragma unroll
    for (int ni = 0; ni < 4; ni++) {
        const int c = wn * 32 + ni * 8 + 2 * (lane & 3);
        float2 v0 = make_float2(oacc[ni][0] * inv0, oacc[ni][1] * inv0);
        float2 v1 = make_float2(oacc[ni][2] * inv1, oacc[ni][3] * inv1);
        *reinterpret_cast<float2*>(aob + (size_t)r * CDIM + c)       = v0;
        *reinterpret_cast<float2*>(aob + (size_t)(r + 8) * CDIM + c) = v1;
    }
}

// ---------------------------------------------------------------------------
// launcher
// ---------------------------------------------------------------------------
extern "C" void kernel_launch(void* const* d_in, const int* in_sizes, int n_in,
                              void* d_out, int out_size)
{
    (void)in_sizes; (void)n_in; (void)out_size;

    const float* x     = (const float*)d_in[0];
    const float* mask  = (const float*)d_in[1];
    const float* Wqkv  = (const float*)d_in[2];
    const float* Wproj = (const float*)d_in[3];
    const float* bproj = (const float*)d_in[4];
    float* out = (float*)d_out;

    float* qkv = nullptr;
    float* ao  = nullptr;
    cudaGetSymbolAddress((void**)&qkv, g_qkv);
    cudaGetSymbolAddress((void**)&ao,  g_ao);

    cudaFuncSetAttribute(attn_kernel, cudaFuncAttributeMaxDynamicSharedMemorySize, SMEM_BYTES);

    // 1) QKV projection: [16384,1024] x [3072,1024]^T -> g_qkv
    gemm_tf32_kernel<<<dim3(3 * CDIM / GBN, (BATCH * NSEQ) / GBM), 256>>>(
        x, Wqkv, qkv, nullptr, CDIM, 3 * CDIM);

    // 2) fused attention -> g_ao
    attn_kernel<<<dim3(NSEQ / 64, BATCH * NHEAD), 256, SMEM_BYTES>>>(mask);

    // 3) output projection (+bias): [16384,1024] x [1024,1024]^T -> out
    gemm_tf32_kernel<<<dim3(CDIM / GBN, (BATCH * NSEQ) / GBM), 256>>>(
        ao, Wproj, out, bproj, CDIM, CDIM);
}